// round 11
// baseline (speedup 1.0000x reference)
#include <cuda_runtime.h>
#include <cuda_bf16.h>
#include <math.h>

#define NN 50000
#define EE 800000
#define IN_DIM 128
#define FD 64
#define CAT 192
#define OUTD 16

#define SCHUNK 2048
#define CPS 25            // chunks per set
#define NSCB (3 * CPS)    // 75 scan blocks
#define TP 200            // padded tile row (floats)

// ---------------------------------------------------------------------------
__device__ __align__(16) float g_deg[3 * NN];      // w-sums -> dis in place
__device__ __align__(16) float g_selfn[3 * NN];
__device__ __align__(16) int   g_cnt[3 * NN];
__device__ __align__(16) int   g_off[3 * (NN + 1)];
__device__ __align__(16) int   g_rank[3 * EE];     // per-edge rank within dest
__device__ __align__(16) int   g_bsum[NSCB];
__device__ int g_done;
__device__ __align__(16) int2  g_pay[3 * EE];      // (src, w*dis[src]) partial norm
__device__ __align__(16) float g_h[NN * FD];
__device__ __align__(16) float g_h2[NN * FD];

// ---------------------------------------------------------------------------
// degree accumulation + histogram; atomic RETURN captured as per-edge rank
// ---------------------------------------------------------------------------
__global__ void k_deg_cnt(const int* __restrict__ c0,
                          const int* __restrict__ c1,
                          const int* __restrict__ c2,
                          const float* __restrict__ w1,
                          const float* __restrict__ w2) {
    int e = blockIdx.x * blockDim.x + threadIdx.x;
    if (e >= EE) return;
    int a = c0[e], b = c1[e], c = c2[e];
    g_rank[e]          = atomicAdd(&g_cnt[a], 1);
    g_rank[EE + e]     = atomicAdd(&g_cnt[NN + b], 1);
    g_rank[2 * EE + e] = atomicAdd(&g_cnt[2 * NN + c], 1);
    atomicAdd(&g_deg[NN + b], w1[e]);
    atomicAdd(&g_deg[2 * NN + c], w2[e]);
}

// ---------------------------------------------------------------------------
// Single-pass scan: local exclusive scan + dis/selfn, spin-sync on 75 blocks.
// ---------------------------------------------------------------------------
__global__ __launch_bounds__(256) void k_scan() {
    const int b = blockIdx.x;
    const int set = b / CPS, ci = b - set * CPS;
    const int* cnt = g_cnt + set * NN;
    int* off = g_off + set * (NN + 1);
    const int tbase = ci * SCHUNK + threadIdx.x * 8;
    const int lane = threadIdx.x & 31, wid = threadIdx.x >> 5;

    int v[8];
#pragma unroll
    for (int i = 0; i < 8; i++) {
        int idx = tbase + i;
        if (idx < NN) {
            int gi = set * NN + idx;
            int c = cnt[idx];
            v[i] = c;
            float d = (set == 0) ? (float)(c + 1) : (g_deg[gi] + 1.0f);
            float dis = rsqrtf(d);
            g_deg[gi] = dis;
            g_selfn[gi] = dis * dis;
        } else {
            v[i] = 0;
        }
    }
    int s = 0;
#pragma unroll
    for (int i = 0; i < 8; i++) s += v[i];

    int inc = s;
#pragma unroll
    for (int o = 1; o < 32; o <<= 1) {
        int n = __shfl_up_sync(0xffffffff, inc, o);
        if (lane >= o) inc += n;
    }
    __shared__ int wsum[8];
    __shared__ int sh_base;
    if (lane == 31) wsum[wid] = inc;
    __syncthreads();
    if (wid == 0) {
        int w = (lane < 8) ? wsum[lane] : 0;
#pragma unroll
        for (int o = 1; o < 8; o <<= 1) {
            int n = __shfl_up_sync(0xffffffff, w, o);
            if (lane >= o) w += n;
        }
        if (lane < 8) wsum[lane] = w;
    }
    __syncthreads();
    const int block_total = wsum[7];

    if (threadIdx.x == 0) {
        g_bsum[b] = block_total;
        __threadfence();
        atomicAdd(&g_done, 1);
        while (atomicAdd(&g_done, 0) < NSCB) { }
        __threadfence();
    }
    __syncthreads();

    if (wid == 0) {
        int bs = (lane < ci) ? g_bsum[set * CPS + lane] : 0;
#pragma unroll
        for (int o = 16; o > 0; o >>= 1) bs += __shfl_down_sync(0xffffffff, bs, o);
        if (lane == 0) sh_base = bs;
    }
    __syncthreads();
    const int base = sh_base;

    if (threadIdx.x == 0 && ci == CPS - 1) off[NN] = base + block_total;

    int run = inc - s + ((wid > 0) ? wsum[wid - 1] : 0) + base;
#pragma unroll
    for (int i = 0; i < 8; i++) {
        int idx = tbase + i;
        if (idx < NN) { off[idx] = run; run += v[i]; }
    }
}

// ---------------------------------------------------------------------------
// Fill: NO atomics (rank from deg_cnt), NO dis[c] gather (partial norm only).
// payload = (src, w * dis[src]); dest factor applied in agg.
// ---------------------------------------------------------------------------
__global__ void k_fill(const int* __restrict__ r0, const int* __restrict__ c0,
                       const int* __restrict__ r1, const int* __restrict__ c1,
                       const int* __restrict__ r2, const int* __restrict__ c2,
                       const float* __restrict__ w1, const float* __restrict__ w2) {
    int e = blockIdx.x * blockDim.x + threadIdx.x;
    if (e >= EE) return;
    const float* dis0 = g_deg;
    const float* dis1 = g_deg + NN;
    const float* dis2 = g_deg + 2 * NN;
    {
        int r = r0[e];
        int p = g_off[c0[e]] + g_rank[e];
        g_pay[p] = make_int2(r, __float_as_int(dis0[r]));
    }
    {
        int r = r1[e];
        int p = g_off[(NN + 1) + c1[e]] + g_rank[EE + e];
        g_pay[EE + p] = make_int2(r, __float_as_int(w1[e] * dis1[r]));
    }
    {
        int r = r2[e];
        int p = g_off[2 * (NN + 1) + c2[e]] + g_rank[2 * EE + e];
        g_pay[2 * EE + p] = make_int2(r, __float_as_int(w2[e] * dis2[r]));
    }
}

// ---------------------------------------------------------------------------
// GEMM layer 1: h = x @ lin1^T  (K=128), 128x64 tile, 8x4 micro-tile.
// ---------------------------------------------------------------------------
__global__ __launch_bounds__(256) void k_gemm1(const float* __restrict__ A,
                                               const float* __restrict__ W,
                                               float* __restrict__ C) {
    __shared__ float4 As4[128][16];
    __shared__ float4 Ws4[16][4][16];
    const int row0 = blockIdx.x * 128;
    const int rg = threadIdx.x >> 4;
    const int cg = threadIdx.x & 15;

    float4 acc[8];
#pragma unroll
    for (int r = 0; r < 8; r++) acc[r] = make_float4(0.f, 0.f, 0.f, 0.f);

    for (int kc = 0; kc < IN_DIM; kc += 64) {
#pragma unroll
        for (int e = threadIdx.x; e < 128 * 16; e += 256) {
            int r = e >> 4, q = e & 15;
            int row = row0 + r;
            float4 v = make_float4(0.f, 0.f, 0.f, 0.f);
            if (row < NN)
                v = *reinterpret_cast<const float4*>(A + (size_t)row * IN_DIM + kc + q * 4);
            As4[r][q] = v;
        }
#pragma unroll
        for (int e = threadIdx.x; e < 64 * 16; e += 256) {
            int f = e & 63, k4 = e >> 6;
            float4 v = *reinterpret_cast<const float4*>(W + (size_t)f * IN_DIM + kc + k4 * 4);
            Ws4[k4][f & 3][f >> 2] = v;
        }
        __syncthreads();
#pragma unroll
        for (int k4 = 0; k4 < 16; k4++) {
            float4 a[8];
#pragma unroll
            for (int r = 0; r < 8; r++) a[r] = As4[rg * 8 + r][k4];
            float4 w0 = Ws4[k4][0][cg];
            float4 w1 = Ws4[k4][1][cg];
            float4 w2 = Ws4[k4][2][cg];
            float4 w3 = Ws4[k4][3][cg];
#pragma unroll
            for (int r = 0; r < 8; r++) {
                acc[r].x = fmaf(a[r].x, w0.x, acc[r].x);
                acc[r].x = fmaf(a[r].y, w0.y, acc[r].x);
                acc[r].x = fmaf(a[r].z, w0.z, acc[r].x);
                acc[r].x = fmaf(a[r].w, w0.w, acc[r].x);
                acc[r].y = fmaf(a[r].x, w1.x, acc[r].y);
                acc[r].y = fmaf(a[r].y, w1.y, acc[r].y);
                acc[r].y = fmaf(a[r].z, w1.z, acc[r].y);
                acc[r].y = fmaf(a[r].w, w1.w, acc[r].y);
                acc[r].z = fmaf(a[r].x, w2.x, acc[r].z);
                acc[r].z = fmaf(a[r].y, w2.y, acc[r].z);
                acc[r].z = fmaf(a[r].z, w2.z, acc[r].z);
                acc[r].z = fmaf(a[r].w, w2.w, acc[r].z);
                acc[r].w = fmaf(a[r].x, w3.x, acc[r].w);
                acc[r].w = fmaf(a[r].y, w3.y, acc[r].w);
                acc[r].w = fmaf(a[r].z, w3.z, acc[r].w);
                acc[r].w = fmaf(a[r].w, w3.w, acc[r].w);
            }
        }
        __syncthreads();
    }
#pragma unroll
    for (int r = 0; r < 8; r++) {
        int row = row0 + rg * 8 + r;
        if (row < NN)
            *reinterpret_cast<float4*>(C + (size_t)row * FD + cg * 4) = acc[r];
    }
}

// ---------------------------------------------------------------------------
// Phase-1 gather: acc = sum(w*dis[r]*h[r]); out = relu(bias + sn*h_n + dc*acc)
// ---------------------------------------------------------------------------
__device__ __forceinline__ void agg_phase1(float* tile, int* s_next, int row0,
                                           const float* __restrict__ h,
                                           const float* __restrict__ bias) {
    const int lane = threadIdx.x & 31;
    for (;;) {
        int g;
        if (lane == 0) g = atomicAdd(s_next, 1);
        g = __shfl_sync(0xffffffff, g, 0);
        if (g >= 96) break;
        const int set = g >> 5;
        const int nl = g & 31;
        const int node = row0 + nl;
        if (node >= NN) continue;

        const int* off = g_off + set * (NN + 1);
        const int start = __ldg(&off[node]);
        const int end = __ldg(&off[node + 1]);
        const float sn = g_selfn[set * NN + node];
        const float dc = g_deg[set * NN + node];   // dis at destination

        float2 acc = make_float2(0.0f, 0.0f);
        const int2* pay = g_pay + (size_t)set * EE;
        int p = start;
        for (; p + 4 <= end; p += 4) {
            int2 e0 = __ldg(&pay[p]);
            int2 e1 = __ldg(&pay[p + 1]);
            int2 e2 = __ldg(&pay[p + 2]);
            int2 e3 = __ldg(&pay[p + 3]);
            float2 h0 = *reinterpret_cast<const float2*>(h + (size_t)e0.x * FD + lane * 2);
            float2 h1 = *reinterpret_cast<const float2*>(h + (size_t)e1.x * FD + lane * 2);
            float2 h2 = *reinterpret_cast<const float2*>(h + (size_t)e2.x * FD + lane * 2);
            float2 h3 = *reinterpret_cast<const float2*>(h + (size_t)e3.x * FD + lane * 2);
            float n0 = __int_as_float(e0.y), n1 = __int_as_float(e1.y);
            float n2 = __int_as_float(e2.y), n3 = __int_as_float(e3.y);
            acc.x = fmaf(n0, h0.x, acc.x); acc.y = fmaf(n0, h0.y, acc.y);
            acc.x = fmaf(n1, h1.x, acc.x); acc.y = fmaf(n1, h1.y, acc.y);
            acc.x = fmaf(n2, h2.x, acc.x); acc.y = fmaf(n2, h2.y, acc.y);
            acc.x = fmaf(n3, h3.x, acc.x); acc.y = fmaf(n3, h3.y, acc.y);
        }
        for (; p < end; p++) {
            int2 ed = __ldg(&pay[p]);
            float nv = __int_as_float(ed.y);
            float2 hv = *reinterpret_cast<const float2*>(h + (size_t)ed.x * FD + lane * 2);
            acc.x = fmaf(nv, hv.x, acc.x);
            acc.y = fmaf(nv, hv.y, acc.y);
        }
        float2 bs = *reinterpret_cast<const float2*>(bias + lane * 2);
        float2 hn = *reinterpret_cast<const float2*>(h + (size_t)node * FD + lane * 2);
        float ox = fmaf(dc, acc.x, fmaf(sn, hn.x, bs.x));
        float oy = fmaf(dc, acc.y, fmaf(sn, hn.y, bs.y));
        float2 r2v = make_float2(fmaxf(ox, 0.0f), fmaxf(oy, 0.0f));
        *reinterpret_cast<float2*>(tile + nl * TP + set * FD + lane * 2) = r2v;
    }
}

// ---------------------------------------------------------------------------
// Fused: agg(layer1) tile -> gemm2 -> h2
// ---------------------------------------------------------------------------
__global__ __launch_bounds__(256) void k_fused2(const float* __restrict__ h,
                                                const float* __restrict__ bias,
                                                const float* __restrict__ W,
                                                float* __restrict__ C) {
    __shared__ float tile[32 * TP];
    __shared__ float Ws[64][65];
    __shared__ int s_next;
    const int row0 = blockIdx.x * 32;
    if (threadIdx.x == 0) s_next = 0;
    __syncthreads();

    agg_phase1(tile, &s_next, row0, h, bias);

    const int f = threadIdx.x & 63;
    const int rq = threadIdx.x >> 6;
    float acc[8];
#pragma unroll
    for (int r = 0; r < 8; r++) acc[r] = 0.0f;

    for (int kc = 0; kc < CAT; kc += 64) {
        __syncthreads();
        for (int i = threadIdx.x; i < 64 * 64; i += 256) {
            int ff = i >> 6, kk = i & 63;
            Ws[kk][ff] = W[ff * CAT + kc + kk];
        }
        __syncthreads();
#pragma unroll
        for (int kk = 0; kk < 64; kk += 4) {
            float4 a[8];
#pragma unroll
            for (int r = 0; r < 8; r++)
                a[r] = *reinterpret_cast<const float4*>(&tile[(rq * 8 + r) * TP + kc + kk]);
            float w0 = Ws[kk + 0][f], w1 = Ws[kk + 1][f];
            float w2 = Ws[kk + 2][f], w3 = Ws[kk + 3][f];
#pragma unroll
            for (int r = 0; r < 8; r++) {
                acc[r] = fmaf(w0, a[r].x, acc[r]);
                acc[r] = fmaf(w1, a[r].y, acc[r]);
                acc[r] = fmaf(w2, a[r].z, acc[r]);
                acc[r] = fmaf(w3, a[r].w, acc[r]);
            }
        }
    }
#pragma unroll
    for (int r = 0; r < 8; r++) {
        int row = row0 + rq * 8 + r;
        if (row < NN) C[(size_t)row * FD + f] = acc[r];
    }
}

// ---------------------------------------------------------------------------
// Fused: agg(layer2) tile -> head conv -> log_softmax -> out
// ---------------------------------------------------------------------------
__global__ __launch_bounds__(256) void k_fusedhead(const float* __restrict__ h,
                                                   const float* __restrict__ bias,
                                                   const float* __restrict__ convw,
                                                   const float* __restrict__ convb,
                                                   float* __restrict__ out) {
    __shared__ float tile[32 * TP];
    __shared__ float Wh[CAT * OUTD];
    __shared__ int s_next;
    const int row0 = blockIdx.x * 32;
    if (threadIdx.x == 0) s_next = 0;
    for (int i = threadIdx.x; i < CAT * OUTD; i += 256) {
        int j = i / CAT, k = i - j * CAT;
        Wh[k * OUTD + j] = convw[(size_t)j * CAT + k];
    }
    __syncthreads();

    agg_phase1(tile, &s_next, row0, h, bias);
    __syncthreads();

    const int rl = threadIdx.x >> 4;
    const int j = threadIdx.x & 15;
#pragma unroll
    for (int half = 0; half < 2; half++) {
        int nl = half * 16 + rl;
        int row = row0 + nl;
        if (row < NN) {
            const float4* hr = reinterpret_cast<const float4*>(tile + nl * TP);
            float acc = convb[j];
#pragma unroll 12
            for (int k4 = 0; k4 < CAT / 4; k4++) {
                float4 hv = hr[k4];
                int k = k4 * 4;
                acc = fmaf(hv.x, Wh[(k + 0) * OUTD + j], acc);
                acc = fmaf(hv.y, Wh[(k + 1) * OUTD + j], acc);
                acc = fmaf(hv.z, Wh[(k + 2) * OUTD + j], acc);
                acc = fmaf(hv.w, Wh[(k + 3) * OUTD + j], acc);
            }
            float m = acc;
#pragma unroll
            for (int o = 8; o > 0; o >>= 1)
                m = fmaxf(m, __shfl_xor_sync(0xffffffff, m, o, 16));
            float ex = __expf(acc - m);
            float s = ex;
#pragma unroll
            for (int o = 8; o > 0; o >>= 1)
                s += __shfl_xor_sync(0xffffffff, s, o, 16);
            out[(size_t)row * OUTD + j] = acc - m - __logf(s);
        }
    }
}

// ---------------------------------------------------------------------------
extern "C" void kernel_launch(void* const* d_in, const int* in_sizes, int n_in,
                              void* d_out, int out_size) {
    const float* x     = (const float*)d_in[0];
    const int*   ei    = (const int*)d_in[1];
    const int*   e_in  = (const int*)d_in[2];
    const int*   e_out = (const int*)d_in[3];
    const float* in_w  = (const float*)d_in[4];
    const float* out_w = (const float*)d_in[5];
    const float* lin1  = (const float*)d_in[6];
    const float* lin2  = (const float*)d_in[7];
    const float* b1    = (const float*)d_in[8];
    const float* b2    = (const float*)d_in[9];
    const float* convw = (const float*)d_in[10];
    const float* convb = (const float*)d_in[11];
    float* out = (float*)d_out;
    (void)in_sizes; (void)n_in; (void)out_size;

    const int* r0 = ei;    const int* c0 = ei + EE;
    const int* r1 = e_in;  const int* c1 = e_in + EE;
    const int* r2 = e_out; const int* c2 = e_out + EE;

    static float *p_h = nullptr, *p_h2 = nullptr, *p_deg = nullptr;
    static int *p_cnt = nullptr, *p_done = nullptr;
    static cudaStream_t s1 = nullptr;
    static cudaEvent_t ev_root = nullptr, ev_g1 = nullptr;
    if (!p_h) {
        cudaGetSymbolAddress((void**)&p_h, g_h);
        cudaGetSymbolAddress((void**)&p_h2, g_h2);
        cudaGetSymbolAddress((void**)&p_deg, g_deg);
        cudaGetSymbolAddress((void**)&p_cnt, g_cnt);
        cudaGetSymbolAddress((void**)&p_done, g_done);
        cudaStreamCreateWithFlags(&s1, cudaStreamNonBlocking);
        cudaEventCreateWithFlags(&ev_root, cudaEventDisableTiming);
        cudaEventCreateWithFlags(&ev_g1, cudaEventDisableTiming);
    }

    const int tile_grid = (NN + 31) / 32;
    const int g1_grid = (NN + 127) / 128;

    cudaEventRecord(ev_root, 0);
    cudaStreamWaitEvent(s1, ev_root, 0);

    cudaMemsetAsync(p_deg, 0, 3 * NN * sizeof(float), 0);
    cudaMemsetAsync(p_cnt, 0, 3 * NN * sizeof(int), 0);
    cudaMemsetAsync(p_done, 0, sizeof(int), 0);

    k_deg_cnt<<<(EE + 255) / 256, 256>>>(c0, c1, c2, in_w, out_w);          // 1
    k_scan<<<NSCB, 256>>>();                                                // 2
    k_gemm1<<<g1_grid, 256, 0, s1>>>(x, lin1, p_h);                         // 3 (side)
    cudaEventRecord(ev_g1, s1);
    k_fill<<<(EE + 255) / 256, 256>>>(r0, c0, r1, c1, r2, c2, in_w, out_w); // 4 (profiled)

    cudaStreamWaitEvent(0, ev_g1, 0);
    k_fused2<<<tile_grid, 256>>>(p_h, b1, lin2, p_h2);
    k_fusedhead<<<tile_grid, 256>>>(p_h2, b2, convw, convb, out);
}

// round 12
// speedup vs baseline: 1.0045x; 1.0045x over previous
#include <cuda_runtime.h>
#include <cuda_bf16.h>
#include <math.h>

#define NN 50000
#define EE 800000
#define IN_DIM 128
#define FD 64
#define CAT 192
#define OUTD 16

#define SCHUNK 2048
#define CPS 25            // chunks per set
#define NSCB (3 * CPS)    // 75 scan blocks
#define TP 200            // padded tile row (floats)

// ---------------------------------------------------------------------------
__device__ __align__(16) float g_deg[3 * NN];      // w-sums -> dis in place
__device__ __align__(16) float g_selfn[3 * NN];
__device__ __align__(16) int   g_cnt[3 * NN];
__device__ __align__(16) int   g_off[3 * (NN + 1)];
__device__ __align__(16) int   g_cur[3 * NN];
__device__ __align__(16) int   g_bsum[NSCB];
__device__ int g_done;
__device__ __align__(16) int2  g_pay[3 * EE];      // (src, w*dis[src]) partial norm
__device__ __align__(16) float g_h[NN * FD];
__device__ __align__(16) float g_h2[NN * FD];

// ---------------------------------------------------------------------------
// degree accumulation + histogram (no-return atomics -> REDG)
// ---------------------------------------------------------------------------
__global__ void k_deg_cnt(const int* __restrict__ c0,
                          const int* __restrict__ c1,
                          const int* __restrict__ c2,
                          const float* __restrict__ w1,
                          const float* __restrict__ w2) {
    int e = blockIdx.x * blockDim.x + threadIdx.x;
    if (e >= EE) return;
    int a = c0[e], b = c1[e], c = c2[e];
    atomicAdd(&g_cnt[a], 1);
    atomicAdd(&g_deg[NN + b], w1[e]);     atomicAdd(&g_cnt[NN + b], 1);
    atomicAdd(&g_deg[2 * NN + c], w2[e]); atomicAdd(&g_cnt[2 * NN + c], 1);
}

// ---------------------------------------------------------------------------
// Single-pass scan: local exclusive scan + dis/selfn, spin-sync on 75 blocks.
// Writes off[] and cur[].
// ---------------------------------------------------------------------------
__global__ __launch_bounds__(256) void k_scan() {
    const int b = blockIdx.x;
    const int set = b / CPS, ci = b - set * CPS;
    const int* cnt = g_cnt + set * NN;
    int* off = g_off + set * (NN + 1);
    int* cur = g_cur + set * NN;
    const int tbase = ci * SCHUNK + threadIdx.x * 8;
    const int lane = threadIdx.x & 31, wid = threadIdx.x >> 5;

    int v[8];
#pragma unroll
    for (int i = 0; i < 8; i++) {
        int idx = tbase + i;
        if (idx < NN) {
            int gi = set * NN + idx;
            int c = cnt[idx];
            v[i] = c;
            float d = (set == 0) ? (float)(c + 1) : (g_deg[gi] + 1.0f);
            float dis = rsqrtf(d);
            g_deg[gi] = dis;
            g_selfn[gi] = dis * dis;
        } else {
            v[i] = 0;
        }
    }
    int s = 0;
#pragma unroll
    for (int i = 0; i < 8; i++) s += v[i];

    int inc = s;
#pragma unroll
    for (int o = 1; o < 32; o <<= 1) {
        int n = __shfl_up_sync(0xffffffff, inc, o);
        if (lane >= o) inc += n;
    }
    __shared__ int wsum[8];
    __shared__ int sh_base;
    if (lane == 31) wsum[wid] = inc;
    __syncthreads();
    if (wid == 0) {
        int w = (lane < 8) ? wsum[lane] : 0;
#pragma unroll
        for (int o = 1; o < 8; o <<= 1) {
            int n = __shfl_up_sync(0xffffffff, w, o);
            if (lane >= o) w += n;
        }
        if (lane < 8) wsum[lane] = w;
    }
    __syncthreads();
    const int block_total = wsum[7];

    if (threadIdx.x == 0) {
        g_bsum[b] = block_total;
        __threadfence();
        atomicAdd(&g_done, 1);
        while (atomicAdd(&g_done, 0) < NSCB) { }
        __threadfence();
    }
    __syncthreads();

    if (wid == 0) {
        int bs = (lane < ci) ? g_bsum[set * CPS + lane] : 0;
#pragma unroll
        for (int o = 16; o > 0; o >>= 1) bs += __shfl_down_sync(0xffffffff, bs, o);
        if (lane == 0) sh_base = bs;
    }
    __syncthreads();
    const int base = sh_base;

    if (threadIdx.x == 0 && ci == CPS - 1) off[NN] = base + block_total;

    int run = inc - s + ((wid > 0) ? wsum[wid - 1] : 0) + base;
#pragma unroll
    for (int i = 0; i < 8; i++) {
        int idx = tbase + i;
        if (idx < NN) { off[idx] = run; cur[idx] = run; run += v[i]; }
    }
}

// ---------------------------------------------------------------------------
// Fill: cursor atomics for slot claim; payload stores PARTIAL norm
// (src, w * dis[src]); destination dis factor applied in agg.
// ---------------------------------------------------------------------------
__global__ void k_fill(const int* __restrict__ r0, const int* __restrict__ c0,
                       const int* __restrict__ r1, const int* __restrict__ c1,
                       const int* __restrict__ r2, const int* __restrict__ c2,
                       const float* __restrict__ w1, const float* __restrict__ w2) {
    int e = blockIdx.x * blockDim.x + threadIdx.x;
    if (e >= EE) return;
    const float* dis0 = g_deg;
    const float* dis1 = g_deg + NN;
    const float* dis2 = g_deg + 2 * NN;
    {
        int r = r0[e];
        int p = atomicAdd(&g_cur[c0[e]], 1);
        g_pay[p] = make_int2(r, __float_as_int(dis0[r]));
    }
    {
        int r = r1[e];
        int p = atomicAdd(&g_cur[NN + c1[e]], 1);
        g_pay[EE + p] = make_int2(r, __float_as_int(w1[e] * dis1[r]));
    }
    {
        int r = r2[e];
        int p = atomicAdd(&g_cur[2 * NN + c2[e]], 1);
        g_pay[2 * EE + p] = make_int2(r, __float_as_int(w2[e] * dis2[r]));
    }
}

// ---------------------------------------------------------------------------
// GEMM layer 1: h = x @ lin1^T  (K=128), 128x64 tile, 8x4 micro-tile.
// ---------------------------------------------------------------------------
__global__ __launch_bounds__(256) void k_gemm1(const float* __restrict__ A,
                                               const float* __restrict__ W,
                                               float* __restrict__ C) {
    __shared__ float4 As4[128][16];
    __shared__ float4 Ws4[16][4][16];
    const int row0 = blockIdx.x * 128;
    const int rg = threadIdx.x >> 4;
    const int cg = threadIdx.x & 15;

    float4 acc[8];
#pragma unroll
    for (int r = 0; r < 8; r++) acc[r] = make_float4(0.f, 0.f, 0.f, 0.f);

    for (int kc = 0; kc < IN_DIM; kc += 64) {
#pragma unroll
        for (int e = threadIdx.x; e < 128 * 16; e += 256) {
            int r = e >> 4, q = e & 15;
            int row = row0 + r;
            float4 v = make_float4(0.f, 0.f, 0.f, 0.f);
            if (row < NN)
                v = *reinterpret_cast<const float4*>(A + (size_t)row * IN_DIM + kc + q * 4);
            As4[r][q] = v;
        }
#pragma unroll
        for (int e = threadIdx.x; e < 64 * 16; e += 256) {
            int f = e & 63, k4 = e >> 6;
            float4 v = *reinterpret_cast<const float4*>(W + (size_t)f * IN_DIM + kc + k4 * 4);
            Ws4[k4][f & 3][f >> 2] = v;
        }
        __syncthreads();
#pragma unroll
        for (int k4 = 0; k4 < 16; k4++) {
            float4 a[8];
#pragma unroll
            for (int r = 0; r < 8; r++) a[r] = As4[rg * 8 + r][k4];
            float4 w0 = Ws4[k4][0][cg];
            float4 w1 = Ws4[k4][1][cg];
            float4 w2 = Ws4[k4][2][cg];
            float4 w3 = Ws4[k4][3][cg];
#pragma unroll
            for (int r = 0; r < 8; r++) {
                acc[r].x = fmaf(a[r].x, w0.x, acc[r].x);
                acc[r].x = fmaf(a[r].y, w0.y, acc[r].x);
                acc[r].x = fmaf(a[r].z, w0.z, acc[r].x);
                acc[r].x = fmaf(a[r].w, w0.w, acc[r].x);
                acc[r].y = fmaf(a[r].x, w1.x, acc[r].y);
                acc[r].y = fmaf(a[r].y, w1.y, acc[r].y);
                acc[r].y = fmaf(a[r].z, w1.z, acc[r].y);
                acc[r].y = fmaf(a[r].w, w1.w, acc[r].y);
                acc[r].z = fmaf(a[r].x, w2.x, acc[r].z);
                acc[r].z = fmaf(a[r].y, w2.y, acc[r].z);
                acc[r].z = fmaf(a[r].z, w2.z, acc[r].z);
                acc[r].z = fmaf(a[r].w, w2.w, acc[r].z);
                acc[r].w = fmaf(a[r].x, w3.x, acc[r].w);
                acc[r].w = fmaf(a[r].y, w3.y, acc[r].w);
                acc[r].w = fmaf(a[r].z, w3.z, acc[r].w);
                acc[r].w = fmaf(a[r].w, w3.w, acc[r].w);
            }
        }
        __syncthreads();
    }
#pragma unroll
    for (int r = 0; r < 8; r++) {
        int row = row0 + rg * 8 + r;
        if (row < NN)
            *reinterpret_cast<float4*>(C + (size_t)row * FD + cg * 4) = acc[r];
    }
}

// ---------------------------------------------------------------------------
// Phase-1 gather: acc = sum(w*dis[r]*h[r]); out = relu(bias + sn*h_n + dc*acc)
// ---------------------------------------------------------------------------
__device__ __forceinline__ void agg_phase1(float* tile, int* s_next, int row0,
                                           const float* __restrict__ h,
                                           const float* __restrict__ bias) {
    const int lane = threadIdx.x & 31;
    for (;;) {
        int g;
        if (lane == 0) g = atomicAdd(s_next, 1);
        g = __shfl_sync(0xffffffff, g, 0);
        if (g >= 96) break;
        const int set = g >> 5;
        const int nl = g & 31;
        const int node = row0 + nl;
        if (node >= NN) continue;

        const int* off = g_off + set * (NN + 1);
        const int start = __ldg(&off[node]);
        const int end = __ldg(&off[node + 1]);
        const float sn = g_selfn[set * NN + node];
        const float dc = g_deg[set * NN + node];   // dis at destination

        float2 acc = make_float2(0.0f, 0.0f);
        const int2* pay = g_pay + (size_t)set * EE;
        int p = start;
        for (; p + 4 <= end; p += 4) {
            int2 e0 = __ldg(&pay[p]);
            int2 e1 = __ldg(&pay[p + 1]);
            int2 e2 = __ldg(&pay[p + 2]);
            int2 e3 = __ldg(&pay[p + 3]);
            float2 h0 = *reinterpret_cast<const float2*>(h + (size_t)e0.x * FD + lane * 2);
            float2 h1 = *reinterpret_cast<const float2*>(h + (size_t)e1.x * FD + lane * 2);
            float2 h2 = *reinterpret_cast<const float2*>(h + (size_t)e2.x * FD + lane * 2);
            float2 h3 = *reinterpret_cast<const float2*>(h + (size_t)e3.x * FD + lane * 2);
            float n0 = __int_as_float(e0.y), n1 = __int_as_float(e1.y);
            float n2 = __int_as_float(e2.y), n3 = __int_as_float(e3.y);
            acc.x = fmaf(n0, h0.x, acc.x); acc.y = fmaf(n0, h0.y, acc.y);
            acc.x = fmaf(n1, h1.x, acc.x); acc.y = fmaf(n1, h1.y, acc.y);
            acc.x = fmaf(n2, h2.x, acc.x); acc.y = fmaf(n2, h2.y, acc.y);
            acc.x = fmaf(n3, h3.x, acc.x); acc.y = fmaf(n3, h3.y, acc.y);
        }
        for (; p < end; p++) {
            int2 ed = __ldg(&pay[p]);
            float nv = __int_as_float(ed.y);
            float2 hv = *reinterpret_cast<const float2*>(h + (size_t)ed.x * FD + lane * 2);
            acc.x = fmaf(nv, hv.x, acc.x);
            acc.y = fmaf(nv, hv.y, acc.y);
        }
        float2 bs = *reinterpret_cast<const float2*>(bias + lane * 2);
        float2 hn = *reinterpret_cast<const float2*>(h + (size_t)node * FD + lane * 2);
        float ox = fmaf(dc, acc.x, fmaf(sn, hn.x, bs.x));
        float oy = fmaf(dc, acc.y, fmaf(sn, hn.y, bs.y));
        float2 r2v = make_float2(fmaxf(ox, 0.0f), fmaxf(oy, 0.0f));
        *reinterpret_cast<float2*>(tile + nl * TP + set * FD + lane * 2) = r2v;
    }
}

// ---------------------------------------------------------------------------
// Fused: agg(layer1) tile -> gemm2 -> h2
// ---------------------------------------------------------------------------
__global__ __launch_bounds__(256) void k_fused2(const float* __restrict__ h,
                                                const float* __restrict__ bias,
                                                const float* __restrict__ W,
                                                float* __restrict__ C) {
    __shared__ float tile[32 * TP];
    __shared__ float Ws[64][65];
    __shared__ int s_next;
    const int row0 = blockIdx.x * 32;
    if (threadIdx.x == 0) s_next = 0;
    __syncthreads();

    agg_phase1(tile, &s_next, row0, h, bias);

    const int f = threadIdx.x & 63;
    const int rq = threadIdx.x >> 6;
    float acc[8];
#pragma unroll
    for (int r = 0; r < 8; r++) acc[r] = 0.0f;

    for (int kc = 0; kc < CAT; kc += 64) {
        __syncthreads();
        for (int i = threadIdx.x; i < 64 * 64; i += 256) {
            int ff = i >> 6, kk = i & 63;
            Ws[kk][ff] = W[ff * CAT + kc + kk];
        }
        __syncthreads();
#pragma unroll
        for (int kk = 0; kk < 64; kk += 4) {
            float4 a[8];
#pragma unroll
            for (int r = 0; r < 8; r++)
                a[r] = *reinterpret_cast<const float4*>(&tile[(rq * 8 + r) * TP + kc + kk]);
            float w0 = Ws[kk + 0][f], w1 = Ws[kk + 1][f];
            float w2 = Ws[kk + 2][f], w3 = Ws[kk + 3][f];
#pragma unroll
            for (int r = 0; r < 8; r++) {
                acc[r] = fmaf(w0, a[r].x, acc[r]);
                acc[r] = fmaf(w1, a[r].y, acc[r]);
                acc[r] = fmaf(w2, a[r].z, acc[r]);
                acc[r] = fmaf(w3, a[r].w, acc[r]);
            }
        }
    }
#pragma unroll
    for (int r = 0; r < 8; r++) {
        int row = row0 + rq * 8 + r;
        if (row < NN) C[(size_t)row * FD + f] = acc[r];
    }
}

// ---------------------------------------------------------------------------
// Fused: agg(layer2) tile -> head conv -> log_softmax -> out
// ---------------------------------------------------------------------------
__global__ __launch_bounds__(256) void k_fusedhead(const float* __restrict__ h,
                                                   const float* __restrict__ bias,
                                                   const float* __restrict__ convw,
                                                   const float* __restrict__ convb,
                                                   float* __restrict__ out) {
    __shared__ float tile[32 * TP];
    __shared__ float Wh[CAT * OUTD];
    __shared__ int s_next;
    const int row0 = blockIdx.x * 32;
    if (threadIdx.x == 0) s_next = 0;
    for (int i = threadIdx.x; i < CAT * OUTD; i += 256) {
        int j = i / CAT, k = i - j * CAT;
        Wh[k * OUTD + j] = convw[(size_t)j * CAT + k];
    }
    __syncthreads();

    agg_phase1(tile, &s_next, row0, h, bias);
    __syncthreads();

    const int rl = threadIdx.x >> 4;
    const int j = threadIdx.x & 15;
#pragma unroll
    for (int half = 0; half < 2; half++) {
        int nl = half * 16 + rl;
        int row = row0 + nl;
        if (row < NN) {
            const float4* hr = reinterpret_cast<const float4*>(tile + nl * TP);
            float acc = convb[j];
#pragma unroll 12
            for (int k4 = 0; k4 < CAT / 4; k4++) {
                float4 hv = hr[k4];
                int k = k4 * 4;
                acc = fmaf(hv.x, Wh[(k + 0) * OUTD + j], acc);
                acc = fmaf(hv.y, Wh[(k + 1) * OUTD + j], acc);
                acc = fmaf(hv.z, Wh[(k + 2) * OUTD + j], acc);
                acc = fmaf(hv.w, Wh[(k + 3) * OUTD + j], acc);
            }
            float m = acc;
#pragma unroll
            for (int o = 8; o > 0; o >>= 1)
                m = fmaxf(m, __shfl_xor_sync(0xffffffff, m, o, 16));
            float ex = __expf(acc - m);
            float s = ex;
#pragma unroll
            for (int o = 8; o > 0; o >>= 1)
                s += __shfl_xor_sync(0xffffffff, s, o, 16);
            out[(size_t)row * OUTD + j] = acc - m - __logf(s);
        }
    }
}

// ---------------------------------------------------------------------------
extern "C" void kernel_launch(void* const* d_in, const int* in_sizes, int n_in,
                              void* d_out, int out_size) {
    const float* x     = (const float*)d_in[0];
    const int*   ei    = (const int*)d_in[1];
    const int*   e_in  = (const int*)d_in[2];
    const int*   e_out = (const int*)d_in[3];
    const float* in_w  = (const float*)d_in[4];
    const float* out_w = (const float*)d_in[5];
    const float* lin1  = (const float*)d_in[6];
    const float* lin2  = (const float*)d_in[7];
    const float* b1    = (const float*)d_in[8];
    const float* b2    = (const float*)d_in[9];
    const float* convw = (const float*)d_in[10];
    const float* convb = (const float*)d_in[11];
    float* out = (float*)d_out;
    (void)in_sizes; (void)n_in; (void)out_size;

    const int* r0 = ei;    const int* c0 = ei + EE;
    const int* r1 = e_in;  const int* c1 = e_in + EE;
    const int* r2 = e_out; const int* c2 = e_out + EE;

    static float *p_h = nullptr, *p_h2 = nullptr, *p_deg = nullptr;
    static int *p_cnt = nullptr, *p_done = nullptr;
    static cudaStream_t s1 = nullptr;
    static cudaEvent_t ev_root = nullptr, ev_g1 = nullptr;
    if (!p_h) {
        cudaGetSymbolAddress((void**)&p_h, g_h);
        cudaGetSymbolAddress((void**)&p_h2, g_h2);
        cudaGetSymbolAddress((void**)&p_deg, g_deg);
        cudaGetSymbolAddress((void**)&p_cnt, g_cnt);
        cudaGetSymbolAddress((void**)&p_done, g_done);
        cudaStreamCreateWithFlags(&s1, cudaStreamNonBlocking);
        cudaEventCreateWithFlags(&ev_root, cudaEventDisableTiming);
        cudaEventCreateWithFlags(&ev_g1, cudaEventDisableTiming);
    }

    const int tile_grid = (NN + 31) / 32;
    const int g1_grid = (NN + 127) / 128;

    cudaEventRecord(ev_root, 0);
    cudaStreamWaitEvent(s1, ev_root, 0);

    cudaMemsetAsync(p_deg, 0, 3 * NN * sizeof(float), 0);
    cudaMemsetAsync(p_cnt, 0, 3 * NN * sizeof(int), 0);
    cudaMemsetAsync(p_done, 0, sizeof(int), 0);

    k_deg_cnt<<<(EE + 255) / 256, 256>>>(c0, c1, c2, in_w, out_w);          // 1
    k_scan<<<NSCB, 256>>>();                                                // 2
    k_gemm1<<<g1_grid, 256, 0, s1>>>(x, lin1, p_h);                         // 3 (side)
    cudaEventRecord(ev_g1, s1);
    k_fill<<<(EE + 255) / 256, 256>>>(r0, c0, r1, c1, r2, c2, in_w, out_w); // 4 (profiled)

    cudaStreamWaitEvent(0, ev_g1, 0);
    k_fused2<<<tile_grid, 256>>>(p_h, b1, lin2, p_h2);
    k_fusedhead<<<tile_grid, 256>>>(p_h2, b2, convw, convb, out);
}

// round 13
// speedup vs baseline: 1.0954x; 1.0905x over previous
#include <cuda_runtime.h>
#include <cuda_fp16.h>
#include <math.h>

#define NN 50000
#define EE 800000
#define IN_DIM 128
#define FD 64
#define CAT 192
#define OUTD 16

#define SCHUNK 2048
#define CPS 25            // chunks per set
#define NSCB (3 * CPS)    // 75 scan blocks
#define TP 200            // padded tile row (floats)

// ---------------------------------------------------------------------------
__device__ __align__(16) float  g_deg[3 * NN];      // w-sums -> dis in place
__device__ __align__(16) float  g_selfn[3 * NN];
__device__ __align__(16) int    g_cnt[3 * NN];
__device__ __align__(16) int    g_off[3 * (NN + 1)];
__device__ __align__(16) int    g_cur[3 * NN];
__device__ __align__(16) int    g_bsum[NSCB];
__device__ int g_done;
__device__ __align__(16) int2   g_pay[3 * EE];      // (src, full norm)
__device__ __align__(16) __half g_h[NN * FD];       // fp16 features (layer 1)
__device__ __align__(16) __half g_h2[NN * FD];      // fp16 features (layer 2)

// ---------------------------------------------------------------------------
__global__ void k_deg_cnt(const int* __restrict__ c0,
                          const int* __restrict__ c1,
                          const int* __restrict__ c2,
                          const float* __restrict__ w1,
                          const float* __restrict__ w2) {
    int e = blockIdx.x * blockDim.x + threadIdx.x;
    if (e >= EE) return;
    int a = c0[e], b = c1[e], c = c2[e];
    atomicAdd(&g_cnt[a], 1);
    atomicAdd(&g_deg[NN + b], w1[e]);     atomicAdd(&g_cnt[NN + b], 1);
    atomicAdd(&g_deg[2 * NN + c], w2[e]); atomicAdd(&g_cnt[2 * NN + c], 1);
}

// ---------------------------------------------------------------------------
// Single-pass scan: local exclusive scan + dis/selfn, spin-sync on 75 blocks.
// ---------------------------------------------------------------------------
__global__ __launch_bounds__(256) void k_scan() {
    const int b = blockIdx.x;
    const int set = b / CPS, ci = b - set * CPS;
    const int* cnt = g_cnt + set * NN;
    int* off = g_off + set * (NN + 1);
    int* cur = g_cur + set * NN;
    const int tbase = ci * SCHUNK + threadIdx.x * 8;
    const int lane = threadIdx.x & 31, wid = threadIdx.x >> 5;

    int v[8];
#pragma unroll
    for (int i = 0; i < 8; i++) {
        int idx = tbase + i;
        if (idx < NN) {
            int gi = set * NN + idx;
            int c = cnt[idx];
            v[i] = c;
            float d = (set == 0) ? (float)(c + 1) : (g_deg[gi] + 1.0f);
            float dis = rsqrtf(d);
            g_deg[gi] = dis;
            g_selfn[gi] = dis * dis;
        } else {
            v[i] = 0;
        }
    }
    int s = 0;
#pragma unroll
    for (int i = 0; i < 8; i++) s += v[i];

    int inc = s;
#pragma unroll
    for (int o = 1; o < 32; o <<= 1) {
        int n = __shfl_up_sync(0xffffffff, inc, o);
        if (lane >= o) inc += n;
    }
    __shared__ int wsum[8];
    __shared__ int sh_base;
    if (lane == 31) wsum[wid] = inc;
    __syncthreads();
    if (wid == 0) {
        int w = (lane < 8) ? wsum[lane] : 0;
#pragma unroll
        for (int o = 1; o < 8; o <<= 1) {
            int n = __shfl_up_sync(0xffffffff, w, o);
            if (lane >= o) w += n;
        }
        if (lane < 8) wsum[lane] = w;
    }
    __syncthreads();
    const int block_total = wsum[7];

    if (threadIdx.x == 0) {
        g_bsum[b] = block_total;
        __threadfence();
        atomicAdd(&g_done, 1);
        while (atomicAdd(&g_done, 0) < NSCB) { }
        __threadfence();
    }
    __syncthreads();

    if (wid == 0) {
        int bs = (lane < ci) ? g_bsum[set * CPS + lane] : 0;
#pragma unroll
        for (int o = 16; o > 0; o >>= 1) bs += __shfl_down_sync(0xffffffff, bs, o);
        if (lane == 0) sh_base = bs;
    }
    __syncthreads();
    const int base = sh_base;

    if (threadIdx.x == 0 && ci == CPS - 1) off[NN] = base + block_total;

    int run = inc - s + ((wid > 0) ? wsum[wid - 1] : 0) + base;
#pragma unroll
    for (int i = 0; i < 8; i++) {
        int idx = tbase + i;
        if (idx < NN) { off[idx] = run; cur[idx] = run; run += v[i]; }
    }
}

// ---------------------------------------------------------------------------
// Fill (R10 form): cursor atomics, FULL norm dis[r]*w*dis[c] in payload.
// ---------------------------------------------------------------------------
__global__ void k_fill(const int* __restrict__ r0, const int* __restrict__ c0,
                       const int* __restrict__ r1, const int* __restrict__ c1,
                       const int* __restrict__ r2, const int* __restrict__ c2,
                       const float* __restrict__ w1, const float* __restrict__ w2) {
    int e = blockIdx.x * blockDim.x + threadIdx.x;
    if (e >= EE) return;
    const float* dis0 = g_deg;
    const float* dis1 = g_deg + NN;
    const float* dis2 = g_deg + 2 * NN;
    {
        int r = r0[e], c = c0[e];
        float nv = dis0[r] * dis0[c];
        int p = atomicAdd(&g_cur[c], 1);
        g_pay[p] = make_int2(r, __float_as_int(nv));
    }
    {
        int r = r1[e], c = c1[e];
        float nv = dis1[r] * w1[e] * dis1[c];
        int p = atomicAdd(&g_cur[NN + c], 1);
        g_pay[EE + p] = make_int2(r, __float_as_int(nv));
    }
    {
        int r = r2[e], c = c2[e];
        float nv = dis2[r] * w2[e] * dis2[c];
        int p = atomicAdd(&g_cur[2 * NN + c], 1);
        g_pay[2 * EE + p] = make_int2(r, __float_as_int(nv));
    }
}

// ---------------------------------------------------------------------------
// GEMM layer 1: h = x @ lin1^T  (K=128), 128x64 tile, 8x4 micro-tile.
// Output stored as fp16.
// ---------------------------------------------------------------------------
__global__ __launch_bounds__(256) void k_gemm1(const float* __restrict__ A,
                                               const float* __restrict__ W,
                                               __half* __restrict__ C) {
    __shared__ float4 As4[128][16];
    __shared__ float4 Ws4[16][4][16];
    const int row0 = blockIdx.x * 128;
    const int rg = threadIdx.x >> 4;
    const int cg = threadIdx.x & 15;

    float4 acc[8];
#pragma unroll
    for (int r = 0; r < 8; r++) acc[r] = make_float4(0.f, 0.f, 0.f, 0.f);

    for (int kc = 0; kc < IN_DIM; kc += 64) {
#pragma unroll
        for (int e = threadIdx.x; e < 128 * 16; e += 256) {
            int r = e >> 4, q = e & 15;
            int row = row0 + r;
            float4 v = make_float4(0.f, 0.f, 0.f, 0.f);
            if (row < NN)
                v = *reinterpret_cast<const float4*>(A + (size_t)row * IN_DIM + kc + q * 4);
            As4[r][q] = v;
        }
#pragma unroll
        for (int e = threadIdx.x; e < 64 * 16; e += 256) {
            int f = e & 63, k4 = e >> 6;
            float4 v = *reinterpret_cast<const float4*>(W + (size_t)f * IN_DIM + kc + k4 * 4);
            Ws4[k4][f & 3][f >> 2] = v;
        }
        __syncthreads();
#pragma unroll
        for (int k4 = 0; k4 < 16; k4++) {
            float4 a[8];
#pragma unroll
            for (int r = 0; r < 8; r++) a[r] = As4[rg * 8 + r][k4];
            float4 w0 = Ws4[k4][0][cg];
            float4 w1 = Ws4[k4][1][cg];
            float4 w2 = Ws4[k4][2][cg];
            float4 w3 = Ws4[k4][3][cg];
#pragma unroll
            for (int r = 0; r < 8; r++) {
                acc[r].x = fmaf(a[r].x, w0.x, acc[r].x);
                acc[r].x = fmaf(a[r].y, w0.y, acc[r].x);
                acc[r].x = fmaf(a[r].z, w0.z, acc[r].x);
                acc[r].x = fmaf(a[r].w, w0.w, acc[r].x);
                acc[r].y = fmaf(a[r].x, w1.x, acc[r].y);
                acc[r].y = fmaf(a[r].y, w1.y, acc[r].y);
                acc[r].y = fmaf(a[r].z, w1.z, acc[r].y);
                acc[r].y = fmaf(a[r].w, w1.w, acc[r].y);
                acc[r].z = fmaf(a[r].x, w2.x, acc[r].z);
                acc[r].z = fmaf(a[r].y, w2.y, acc[r].z);
                acc[r].z = fmaf(a[r].z, w2.z, acc[r].z);
                acc[r].z = fmaf(a[r].w, w2.w, acc[r].z);
                acc[r].w = fmaf(a[r].x, w3.x, acc[r].w);
                acc[r].w = fmaf(a[r].y, w3.y, acc[r].w);
                acc[r].w = fmaf(a[r].z, w3.z, acc[r].w);
                acc[r].w = fmaf(a[r].w, w3.w, acc[r].w);
            }
        }
        __syncthreads();
    }
#pragma unroll
    for (int r = 0; r < 8; r++) {
        int row = row0 + rg * 8 + r;
        if (row < NN) {
            __half2* dst = reinterpret_cast<__half2*>(C + (size_t)row * FD + cg * 4);
            dst[0] = __floats2half2_rn(acc[r].x, acc[r].y);
            dst[1] = __floats2half2_rn(acc[r].z, acc[r].w);
        }
    }
}

// ---------------------------------------------------------------------------
// Phase-1 gather (R10 structure, fp16 feature loads):
// acc = bias + selfn*h[node] + sum norm*h[src]; relu; store to smem tile.
// ---------------------------------------------------------------------------
__device__ __forceinline__ void agg_phase1(float* tile, int* s_next, int row0,
                                           const __half* __restrict__ h,
                                           const float* __restrict__ bias) {
    const int lane = threadIdx.x & 31;
    for (;;) {
        int g;
        if (lane == 0) g = atomicAdd(s_next, 1);
        g = __shfl_sync(0xffffffff, g, 0);
        if (g >= 96) break;
        const int set = g >> 5;
        const int nl = g & 31;
        const int node = row0 + nl;
        if (node >= NN) continue;

        const int* off = g_off + set * (NN + 1);
        const int start = __ldg(&off[node]);
        const int end = __ldg(&off[node + 1]);
        const float sn = g_selfn[set * NN + node];

        float2 acc = *reinterpret_cast<const float2*>(bias + lane * 2);
        {
            float2 hv = __half22float2(
                *reinterpret_cast<const __half2*>(h + (size_t)node * FD + lane * 2));
            acc.x = fmaf(sn, hv.x, acc.x);
            acc.y = fmaf(sn, hv.y, acc.y);
        }
        const int2* pay = g_pay + (size_t)set * EE;
        int p = start;
        for (; p + 4 <= end; p += 4) {
            int2 e0 = __ldg(&pay[p]);
            int2 e1 = __ldg(&pay[p + 1]);
            int2 e2 = __ldg(&pay[p + 2]);
            int2 e3 = __ldg(&pay[p + 3]);
            float2 h0 = __half22float2(
                *reinterpret_cast<const __half2*>(h + (size_t)e0.x * FD + lane * 2));
            float2 h1 = __half22float2(
                *reinterpret_cast<const __half2*>(h + (size_t)e1.x * FD + lane * 2));
            float2 h2 = __half22float2(
                *reinterpret_cast<const __half2*>(h + (size_t)e2.x * FD + lane * 2));
            float2 h3 = __half22float2(
                *reinterpret_cast<const __half2*>(h + (size_t)e3.x * FD + lane * 2));
            float n0 = __int_as_float(e0.y), n1 = __int_as_float(e1.y);
            float n2 = __int_as_float(e2.y), n3 = __int_as_float(e3.y);
            acc.x = fmaf(n0, h0.x, acc.x); acc.y = fmaf(n0, h0.y, acc.y);
            acc.x = fmaf(n1, h1.x, acc.x); acc.y = fmaf(n1, h1.y, acc.y);
            acc.x = fmaf(n2, h2.x, acc.x); acc.y = fmaf(n2, h2.y, acc.y);
            acc.x = fmaf(n3, h3.x, acc.x); acc.y = fmaf(n3, h3.y, acc.y);
        }
        for (; p < end; p++) {
            int2 ed = __ldg(&pay[p]);
            float nv = __int_as_float(ed.y);
            float2 hv = __half22float2(
                *reinterpret_cast<const __half2*>(h + (size_t)ed.x * FD + lane * 2));
            acc.x = fmaf(nv, hv.x, acc.x);
            acc.y = fmaf(nv, hv.y, acc.y);
        }
        float2 r2v = make_float2(fmaxf(acc.x, 0.0f), fmaxf(acc.y, 0.0f));
        *reinterpret_cast<float2*>(tile + nl * TP + set * FD + lane * 2) = r2v;
    }
}

// ---------------------------------------------------------------------------
// Fused: agg(layer1) tile -> gemm2 -> h2 (fp16 out)
// ---------------------------------------------------------------------------
__global__ __launch_bounds__(256) void k_fused2(const __half* __restrict__ h,
                                                const float* __restrict__ bias,
                                                const float* __restrict__ W,
                                                __half* __restrict__ C) {
    __shared__ float tile[32 * TP];
    __shared__ float Ws[64][65];
    __shared__ int s_next;
    const int row0 = blockIdx.x * 32;
    if (threadIdx.x == 0) s_next = 0;
    __syncthreads();

    agg_phase1(tile, &s_next, row0, h, bias);

    const int f = threadIdx.x & 63;
    const int rq = threadIdx.x >> 6;
    float acc[8];
#pragma unroll
    for (int r = 0; r < 8; r++) acc[r] = 0.0f;

    for (int kc = 0; kc < CAT; kc += 64) {
        __syncthreads();
        for (int i = threadIdx.x; i < 64 * 64; i += 256) {
            int ff = i >> 6, kk = i & 63;
            Ws[kk][ff] = W[ff * CAT + kc + kk];
        }
        __syncthreads();
#pragma unroll
        for (int kk = 0; kk < 64; kk += 4) {
            float4 a[8];
#pragma unroll
            for (int r = 0; r < 8; r++)
                a[r] = *reinterpret_cast<const float4*>(&tile[(rq * 8 + r) * TP + kc + kk]);
            float w0 = Ws[kk + 0][f], w1 = Ws[kk + 1][f];
            float w2 = Ws[kk + 2][f], w3 = Ws[kk + 3][f];
#pragma unroll
            for (int r = 0; r < 8; r++) {
                acc[r] = fmaf(w0, a[r].x, acc[r]);
                acc[r] = fmaf(w1, a[r].y, acc[r]);
                acc[r] = fmaf(w2, a[r].z, acc[r]);
                acc[r] = fmaf(w3, a[r].w, acc[r]);
            }
        }
    }
#pragma unroll
    for (int r = 0; r < 8; r++) {
        int row = row0 + rq * 8 + r;
        if (row < NN) C[(size_t)row * FD + f] = __float2half_rn(acc[r]);
    }
}

// ---------------------------------------------------------------------------
// Fused: agg(layer2) tile -> head conv -> log_softmax -> out
// ---------------------------------------------------------------------------
__global__ __launch_bounds__(256) void k_fusedhead(const __half* __restrict__ h,
                                                   const float* __restrict__ bias,
                                                   const float* __restrict__ convw,
                                                   const float* __restrict__ convb,
                                                   float* __restrict__ out) {
    __shared__ float tile[32 * TP];
    __shared__ float Wh[CAT * OUTD];
    __shared__ int s_next;
    const int row0 = blockIdx.x * 32;
    if (threadIdx.x == 0) s_next = 0;
    for (int i = threadIdx.x; i < CAT * OUTD; i += 256) {
        int j = i / CAT, k = i - j * CAT;
        Wh[k * OUTD + j] = convw[(size_t)j * CAT + k];
    }
    __syncthreads();

    agg_phase1(tile, &s_next, row0, h, bias);
    __syncthreads();

    const int rl = threadIdx.x >> 4;
    const int j = threadIdx.x & 15;
#pragma unroll
    for (int half = 0; half < 2; half++) {
        int nl = half * 16 + rl;
        int row = row0 + nl;
        if (row < NN) {
            const float4* hr = reinterpret_cast<const float4*>(tile + nl * TP);
            float acc = convb[j];
#pragma unroll 12
            for (int k4 = 0; k4 < CAT / 4; k4++) {
                float4 hv = hr[k4];
                int k = k4 * 4;
                acc = fmaf(hv.x, Wh[(k + 0) * OUTD + j], acc);
                acc = fmaf(hv.y, Wh[(k + 1) * OUTD + j], acc);
                acc = fmaf(hv.z, Wh[(k + 2) * OUTD + j], acc);
                acc = fmaf(hv.w, Wh[(k + 3) * OUTD + j], acc);
            }
            float m = acc;
#pragma unroll
            for (int o = 8; o > 0; o >>= 1)
                m = fmaxf(m, __shfl_xor_sync(0xffffffff, m, o, 16));
            float ex = __expf(acc - m);
            float s = ex;
#pragma unroll
            for (int o = 8; o > 0; o >>= 1)
                s += __shfl_xor_sync(0xffffffff, s, o, 16);
            out[(size_t)row * OUTD + j] = acc - m - __logf(s);
        }
    }
}

// ---------------------------------------------------------------------------
extern "C" void kernel_launch(void* const* d_in, const int* in_sizes, int n_in,
                              void* d_out, int out_size) {
    const float* x     = (const float*)d_in[0];
    const int*   ei    = (const int*)d_in[1];
    const int*   e_in  = (const int*)d_in[2];
    const int*   e_out = (const int*)d_in[3];
    const float* in_w  = (const float*)d_in[4];
    const float* out_w = (const float*)d_in[5];
    const float* lin1  = (const float*)d_in[6];
    const float* lin2  = (const float*)d_in[7];
    const float* b1    = (const float*)d_in[8];
    const float* b2    = (const float*)d_in[9];
    const float* convw = (const float*)d_in[10];
    const float* convb = (const float*)d_in[11];
    float* out = (float*)d_out;
    (void)in_sizes; (void)n_in; (void)out_size;

    const int* r0 = ei;    const int* c0 = ei + EE;
    const int* r1 = e_in;  const int* c1 = e_in + EE;
    const int* r2 = e_out; const int* c2 = e_out + EE;

    static __half *p_h = nullptr, *p_h2 = nullptr;
    static float *p_deg = nullptr;
    static int *p_cnt = nullptr, *p_done = nullptr;
    static cudaStream_t s1 = nullptr;
    static cudaEvent_t ev_root = nullptr, ev_g1 = nullptr;
    if (!p_h) {
        cudaGetSymbolAddress((void**)&p_h, g_h);
        cudaGetSymbolAddress((void**)&p_h2, g_h2);
        cudaGetSymbolAddress((void**)&p_deg, g_deg);
        cudaGetSymbolAddress((void**)&p_cnt, g_cnt);
        cudaGetSymbolAddress((void**)&p_done, g_done);
        cudaStreamCreateWithFlags(&s1, cudaStreamNonBlocking);
        cudaEventCreateWithFlags(&ev_root, cudaEventDisableTiming);
        cudaEventCreateWithFlags(&ev_g1, cudaEventDisableTiming);
    }

    const int tile_grid = (NN + 31) / 32;
    const int g1_grid = (NN + 127) / 128;

    cudaEventRecord(ev_root, 0);
    cudaStreamWaitEvent(s1, ev_root, 0);

    cudaMemsetAsync(p_deg, 0, 3 * NN * sizeof(float), 0);
    cudaMemsetAsync(p_cnt, 0, 3 * NN * sizeof(int), 0);
    cudaMemsetAsync(p_done, 0, sizeof(int), 0);

    k_deg_cnt<<<(EE + 255) / 256, 256>>>(c0, c1, c2, in_w, out_w);          // 1
    k_scan<<<NSCB, 256>>>();                                                // 2
    k_gemm1<<<g1_grid, 256, 0, s1>>>(x, lin1, p_h);                         // 3 (side)
    cudaEventRecord(ev_g1, s1);
    k_fill<<<(EE + 255) / 256, 256>>>(r0, c0, r1, c1, r2, c2, in_w, out_w); // 4 (profiled)

    cudaStreamWaitEvent(0, ev_g1, 0);
    k_fused2<<<tile_grid, 256>>>(p_h, b1, lin2, p_h2);
    k_fusedhead<<<tile_grid, 256>>>(p_h2, b2, convw, convb, out);
}